// round 4
// baseline (speedup 1.0000x reference)
#include <cuda_runtime.h>
#include <math.h>

// Round 3 (complete): fused attention + f32x2 packed matvecs + single node layout.

#define NT 256
#define GRID 148

typedef unsigned long long ull;

#define OFF_WKT   0        // [128][65]
#define OFF_WV    8320     // [64][128]
#define OFF_WO    16512    // [128][64]
#define OFF_BQ    24704
#define OFF_BV    24832
#define OFF_BO    24960
#define OFF_N     25024    // [4][20][68]
#define OFF_RAW   30464    // [192][4] batch-interleaved
#define OFF_Q     31232    // [128][4] batch-interleaved
#define OFF_QK    31744    // [4][8][72]
#define OFF_M     34048    // [4][8][72]
#define OFF_CTX   36352    // [4][128]
#define OFF_RED   36864    // 1024 floats scratch
#define OFF_V     37888    // [4][20]
#define OFF_MASK  37968    // [4][20]
#define SMEM_FLOATS 38048
#define SMEM_BYTES  (SMEM_FLOATS * 4)

__device__ __forceinline__ ull pk1(float a) {
    ull r; asm("mov.b64 %0, {%1,%1};" : "=l"(r) : "f"(a)); return r;
}
__device__ __forceinline__ void fma2(ull& d, ull a, ull b) {
    asm("fma.rn.f32x2 %0, %1, %2, %0;" : "+l"(d) : "l"(a), "l"(b));
}
__device__ __forceinline__ ull add2(ull a, ull b) {
    ull r; asm("add.rn.f32x2 %0, %1, %2;" : "=l"(r) : "l"(a), "l"(b)); return r;
}
__device__ __forceinline__ ull mul2(ull a, ull b) {
    ull r; asm("mul.rn.f32x2 %0, %1, %2;" : "=l"(r) : "l"(a), "l"(b)); return r;
}
__device__ __forceinline__ float2 upk(ull a) {
    float2 f; asm("mov.b64 {%0,%1}, %2;" : "=f"(f.x), "=f"(f.y) : "l"(a)); return f;
}

__global__ void __launch_bounds__(NT, 1)
mha_state_encoder_kernel(const float* __restrict__ node_embed,
                         const int*   __restrict__ start_idx,
                         const int*   __restrict__ end_idx,
                         const int*   __restrict__ pad_idx,
                         const float* __restrict__ Wq, const float* __restrict__ bq,
                         const float* __restrict__ Wk,
                         const float* __restrict__ Wv, const float* __restrict__ bv,
                         const float* __restrict__ Wo, const float* __restrict__ bo,
                         float* __restrict__ out, int B)
{
    extern __shared__ float sm[];
    float* sWKT = sm + OFF_WKT;
    float* sWV  = sm + OFF_WV;
    float* sWO  = sm + OFF_WO;
    float* sBQ  = sm + OFF_BQ;
    float* sBV  = sm + OFF_BV;
    float* sBO  = sm + OFF_BO;
    float* sN   = sm + OFF_N;
    float* sRAW = sm + OFF_RAW;
    float* sQ   = sm + OFF_Q;
    float* sQK  = sm + OFF_QK;
    float* sM   = sm + OFF_M;
    float* sCTX = sm + OFF_CTX;
    float* sRED = sm + OFF_RED;
    float* sV   = sm + OFF_V;
    float* sMASK= sm + OFF_MASK;
    ull*   sRED2 = reinterpret_cast<ull*>(sRED);

    const int t = threadIdx.x;
    const int Q = B >> 2;

    // ---- stage weights ----
    for (int i = t; i < 8192; i += NT) {
        int d = i >> 7, c = i & 127;
        sWKT[c * 65 + d] = Wk[i];
    }
    for (int i = t; i < 2048; i += NT) {
        reinterpret_cast<float4*>(sWV)[i] = reinterpret_cast<const float4*>(Wv)[i];
        reinterpret_cast<float4*>(sWO)[i] = reinterpret_cast<const float4*>(Wo)[i];
    }
    if (t < 128) { sBQ[t] = bq[t]; sBV[t] = bv[t]; }
    if (t < 64)  sBO[t] = bo[t];

    // Wq register slice
    const int c127 = t & 127;
    const int rh   = t >> 7;
    float wq[96];
    {
        const float* src = Wq + (size_t)(rh * 96) * 128 + c127;
        #pragma unroll
        for (int i = 0; i < 96; ++i) wq[i] = src[(size_t)i * 128];
    }

    // gather thread geometry (t in [128,256))
    const int gidx = t - 128;
    const int gnb  = (gidx >> 5) & 3;
    const int gwh  = (gidx >> 4) & 1;
    const int gdq  = gidx & 15;

    // prefetch state
    float4 pfN[5];
    float4 pfG = make_float4(0.f, 0.f, 0.f, 0.f);
    int    pfP = 0, gi_next = 0;

    int q0 = blockIdx.x;
    if (q0 < Q) {
        int b0 = q0 * 4;
        const float4* nsrc = reinterpret_cast<const float4*>(node_embed) + (size_t)b0 * 320;
        #pragma unroll
        for (int k = 0; k < 5; ++k) pfN[k] = nsrc[t + k * 256];
        if (t < 80) pfP = pad_idx[b0 * 20 + t];
        if (t >= 128) {
            int gi = gwh ? end_idx[b0 + gnb] : start_idx[b0 + gnb];
            pfG = *reinterpret_cast<const float4*>(node_embed + (size_t)gi * 64 + gdq * 4);
            int qn = q0 + GRID;
            if (qn < Q) gi_next = gwh ? end_idx[qn * 4 + gnb] : start_idx[qn * 4 + gnb];
        }
    }
    __syncthreads();

    for (int q = q0; q < Q; q += GRID) {
        const int b0 = q * 4;

        // ===== P1: commit prefetched data =====
        {
            float4* sN4 = reinterpret_cast<float4*>(sN);
            #pragma unroll
            for (int k = 0; k < 5; ++k) {
                int g   = t + k * 256;
                int nb  = g / 320;
                int rem = g - nb * 320;
                sN4[nb * 340 + (rem >> 4) * 17 + (rem & 15)] = pfN[k];
            }
            if (t < 80) sV[t] = (pfP >= 0) ? 1.0f : 0.0f;
            if (t >= 128) {
                int r0 = 64 + gwh * 64 + gdq * 4;
                sRAW[(r0 + 0) * 4 + gnb] = pfG.x;
                sRAW[(r0 + 1) * 4 + gnb] = pfG.y;
                sRAW[(r0 + 2) * 4 + gnb] = pfG.z;
                sRAW[(r0 + 3) * 4 + gnb] = pfG.w;
            }
        }
        // issue next-quad prefetch
        {
            int qn = q + GRID;
            if (qn < Q) {
                int bn = qn * 4;
                const float4* nsrc = reinterpret_cast<const float4*>(node_embed) + (size_t)bn * 320;
                #pragma unroll
                for (int k = 0; k < 5; ++k) pfN[k] = nsrc[t + k * 256];
                if (t < 80) pfP = pad_idx[bn * 20 + t];
                if (t >= 128) {
                    pfG = *reinterpret_cast<const float4*>(node_embed + (size_t)gi_next * 64 + gdq * 4);
                    int qn2 = qn + GRID;
                    if (qn2 < Q) gi_next = gwh ? end_idx[qn2 * 4 + gnb] : start_idx[qn2 * 4 + gnb];
                }
            }
        }
        __syncthreads();

        // ===== P2: agg (column sums) + mask (row sums) =====
        if (t < 64) {
            int nb = t >> 4, dq = t & 15;
            const float4* col = reinterpret_cast<const float4*>(sN + nb * 1360) + dq;
            float ax = 0.f, ay = 0.f, az = 0.f, aw = 0.f;
            #pragma unroll
            for (int j = 0; j < 20; ++j) {
                float4 x = col[j * 17];
                ax += x.x; ay += x.y; az += x.z; aw += x.w;
            }
            int r0 = dq * 4;
            sRAW[(r0 + 0) * 4 + nb] = ax;
            sRAW[(r0 + 1) * 4 + nb] = ay;
            sRAW[(r0 + 2) * 4 + nb] = az;
            sRAW[(r0 + 3) * 4 + nb] = aw;
        } else if (t < 144) {
            int idx = t - 64, nb = idx / 20, j = idx - nb * 20;
            const float4* row = reinterpret_cast<const float4*>(sN + nb * 1360 + j * 68);
            float r0 = 0.f, r1 = 0.f;
            #pragma unroll
            for (int k = 0; k < 16; k += 2) {
                float4 a = row[k], b = row[k + 1];
                r0 += (a.x + a.y) + (a.z + a.w);
                r1 += (b.x + b.y) + (b.z + b.w);
            }
            sMASK[idx] = (sV[idx] == 0.f || (r0 + r1) == 0.f) ? 1.0f : 0.0f;
        }
        __syncthreads();

        // ===== P3: q = raw @ Wq  (f32x2, batch-interleaved) =====
        {
            const ulonglong2* pR = reinterpret_cast<const ulonglong2*>(sRAW) + rh * 96;
            ull a01 = 0, a23 = 0;
            #pragma unroll
            for (int i = 0; i < 96; ++i) {
                ulonglong2 x = pR[i];
                ull wp = pk1(wq[i]);
                fma2(a01, wp, x.x);
                fma2(a23, wp, x.y);
            }
            sRED2[rh * 256 + c127 * 2 + 0] = a01;
            sRED2[rh * 256 + c127 * 2 + 1] = a23;
        }
        __syncthreads();
        {   // combine + bias, fold attention scale 0.25 into q
            int c = t >> 1;
            ull v = add2(sRED2[t], sRED2[256 + t]);
            v = add2(v, pk1(sBQ[c]));
            v = mul2(v, pk1(0.25f));
            reinterpret_cast<ull*>(sQ)[t] = v;
        }
        __syncthreads();

        // ===== P4: qk[nb][h][d] = sum_i q[h*16+i][nb] * WkT[h*16+i][d] =====
        #pragma unroll
        for (int p = 0; p < 2; ++p) {
            int u = t + p * 256;
            int h = u >> 6, d = u & 63;
            const float* wkb = sWKT + h * 16 * 65 + d;
            const ulonglong2* q2 = reinterpret_cast<const ulonglong2*>(sQ) + h * 16;
            ull a01 = 0, a23 = 0;
            #pragma unroll
            for (int i = 0; i < 16; ++i) {
                ull wp = pk1(wkb[i * 65]);
                ulonglong2 qv = q2[i];
                fma2(a01, wp, qv.x);
                fma2(a23, wp, qv.y);
            }
            float2 f01 = upk(a01), f23 = upk(a23);
            sQK[0 * 576 + h * 72 + d] = f01.x;
            sQK[1 * 576 + h * 72 + d] = f01.y;
            sQK[2 * 576 + h * 72 + d] = f23.x;
            sQK[3 * 576 + h * 72 + d] = f23.y;
        }
        __syncthreads();

        // ===== Fused attention: scores -> softmax (regs) -> weighted sum =====
        {
            int nb = t >> 6, h = (t >> 3) & 7, dq = t & 7;
            const float* qk = sQK + nb * 576 + h * 72 + dq * 8;
            float4 qa = *reinterpret_cast<const float4*>(qk);
            float4 qb = *reinterpret_cast<const float4*>(qk + 4);
            const float* nbase = sN + nb * 1360 + dq * 8;
            const float* mrow  = sMASK + nb * 20;
            const float* vrow  = sV + nb * 20;

            float sc[20];
            #pragma unroll
            for (int j = 0; j < 20; ++j) {
                const float4* np = reinterpret_cast<const float4*>(nbase + j * 68);
                float4 na = np[0], nb4 = np[1];
                float s = qa.x * na.x;
                s = fmaf(qa.y, na.y, s); s = fmaf(qa.z, na.z, s); s = fmaf(qa.w, na.w, s);
                s = fmaf(qb.x, nb4.x, s); s = fmaf(qb.y, nb4.y, s);
                s = fmaf(qb.z, nb4.z, s); s = fmaf(qb.w, nb4.w, s);
                s += __shfl_xor_sync(0xffffffffu, s, 1);
                s += __shfl_xor_sync(0xffffffffu, s, 2);
                s += __shfl_xor_sync(0xffffffffu, s, 4);
                sc[j] = fmaf(mrow[j], -1e9f, s);
            }
            float mx = sc[0];
            #pragma unroll
            for (int j = 1; j < 20; ++j) mx = fmaxf(mx, sc[j]);
            float ssum = 0.f;
            #pragma unroll
            for (int j = 0; j < 20; ++j) {
                float e = __expf(sc[j] - mx);
                sc[j] = e;
                ssum += e;
            }
            float inv = __fdividef(1.f, ssum);
            float4 ma = make_float4(0.f, 0.f, 0.f, 0.f);
            float4 mb = make_float4(0.f, 0.f, 0.f, 0.f);
            #pragma unroll
            for (int j = 0; j < 20; ++j) {
                float a = sc[j] * inv * vrow[j];
                const float4* np = reinterpret_cast<const float4*>(nbase + j * 68);
                float4 na = np[0], nb4 = np[1];
                ma.x = fmaf(a, na.x, ma.x);  ma.y = fmaf(a, na.y, ma.y);
                ma.z = fmaf(a, na.z, ma.z);  ma.w = fmaf(a, na.w, ma.w);
                mb.x = fmaf(a, nb4.x, mb.x); mb.y = fmaf(a, nb4.y, mb.y);
                mb.z = fmaf(a, nb4.z, mb.z); mb.w = fmaf(a, nb4.w, mb.w);
            }
            float* mdst = sM + nb * 576 + h * 72 + dq * 8;
            *reinterpret_cast<float4*>(mdst)     = ma;
            *reinterpret_cast<float4*>(mdst + 4) = mb;
        }
        __syncthreads();

        // ===== P7: ctx[nb][c] = m[nb][h(c)] . Wv[:,c] + bv =====
        {
            int cc = t & 127, dh = t >> 7, d0 = dh * 32, h = cc >> 4;
            const float* wv = sWV + d0 * 128 + cc;
            float a0 = 0.f, a1 = 0.f, a2 = 0.f, a3 = 0.f;
            #pragma unroll
            for (int k = 0; k < 8; ++k) {
                float w0 = wv[(k*4+0)*128], w1 = wv[(k*4+1)*128];
                float w2 = wv[(k*4+2)*128], w3 = wv[(k*4+3)*128];
                float4 m0 = *reinterpret_cast<const float4*>(sM + 0*576 + h*72 + d0 + k*4);
                float4 m1 = *reinterpret_cast<const float4*>(sM + 1*576 + h*72 + d0 + k*4);
                float4 m2 = *reinterpret_cast<const float4*>(sM + 2*576 + h*72 + d0 + k*4);
                float4 m3 = *reinterpret_cast<const float4*>(sM + 3*576 + h*72 + d0 + k*4);
                a0 = fmaf(w0,m0.x,a0); a0 = fmaf(w1,m0.y,a0); a0 = fmaf(w2,m0.z,a0); a0 = fmaf(w3,m0.w,a0);
                a1 = fmaf(w0,m1.x,a1); a1 = fmaf(w1,m1.y,a1); a1 = fmaf(w2,m1.z,a1); a1 = fmaf(w3,m1.w,a1);
                a2 = fmaf(w0,m2.x,a2); a2 = fmaf(w1,m2.y,a2); a2 = fmaf(w2,m2.z,a2); a2 = fmaf(w3,m2.w,a2);
                a3 = fmaf(w0,m3.x,a3); a3 = fmaf(w1,m3.y,a3); a3 = fmaf(w2,m3.z,a3); a3 = fmaf(w3,m3.w,a3);
            }
            sRED[(dh*4 + 0) * 128 + cc] = a0;
            sRED[(dh*4 + 1) * 128 + cc] = a1;
            sRED[(dh*4 + 2) * 128 + cc] = a2;
            sRED[(dh*4 + 3) * 128 + cc] = a3;
        }
        __syncthreads();
        {
            #pragma unroll
            for (int e = t; e < 512; e += NT) {
                int nb = e >> 7, cc = e & 127;
                sCTX[nb * 128 + cc] = sRED[nb * 128 + cc] + sRED[(4 + nb) * 128 + cc] + sBV[cc];
            }
        }
        __syncthreads();

        // ===== P8: out[nb][o] = ctx . Wo[:,o] + bo =====
        {
            int o = t & 63, cg = t >> 6, c0 = cg * 32;
            const float* wo = sWO + c0 * 64 + o;
            float a0 = 0.f, a1 = 0.f, a2 = 0.f, a3 = 0.f;
            #pragma unroll
            for (int k = 0; k < 8; ++k) {
                float w0 = wo[(k*4+0)*64], w1 = wo[(k*4+1)*64];
                float w2 = wo[(k*4+2)*64], w3 = wo[(k*4+3)*64];
                float4 x0 = *reinterpret_cast<const float4*>(sCTX + 0*128 + c0 + k*4);
                float4 x1 = *reinterpret_cast<const float4*>(sCTX + 1*128 + c0 + k*4);
                float4 x2 = *reinterpret_cast<const float4*>(sCTX + 2*128 + c0 + k*4);
                float4 x3 = *reinterpret_cast<const float4*>(sCTX + 3*128 + c0 + k*4);
                a0 = fmaf(w0,x0.x,a0); a0 = fmaf(w1,x0.y,a0); a0 = fmaf(w2,x0.z,a0); a0 = fmaf(w3,x0.w,a0);
                a1 = fmaf(w0,x1.x,a1); a1 = fmaf(w1,x1.y,a1); a1 = fmaf(w2,x1.z,a1); a1 = fmaf(w3,x1.w,a1);
                a2 = fmaf(w0,x2.x,a2); a2 = fmaf(w1,x2.y,a2); a2 = fmaf(w2,x2.z,a2); a2 = fmaf(w3,x2.w,a2);
                a3 = fmaf(w0,x3.x,a3); a3 = fmaf(w1,x3.y,a3); a3 = fmaf(w2,x3.z,a3); a3 = fmaf(w3,x3.w,a3);
            }
            sRED[(cg*4 + 0) * 64 + o] = a0;
            sRED[(cg*4 + 1) * 64 + o] = a1;
            sRED[(cg*4 + 2) * 64 + o] = a2;
            sRED[(cg*4 + 3) * 64 + o] = a3;
        }
        __syncthreads();
        {
            int nb = t >> 6, o = t & 63;
            float s = ((sRED[(0*4+nb)*64+o] + sRED[(1*4+nb)*64+o]) +
                       (sRED[(2*4+nb)*64+o] + sRED[(3*4+nb)*64+o])) + sBO[o];
            out[(size_t)(b0 + nb) * 64 + o] = s;
        }
    }
}

extern "C" void kernel_launch(void* const* d_in, const int* in_sizes, int n_in,
                              void* d_out, int out_size)
{
    const float* node_embed = (const float*)d_in[0];
    const int*   start_idx  = (const int*)d_in[1];
    const int*   end_idx    = (const int*)d_in[2];
    /* d_in[3] seg_ids unused (structural) */
    const int*   pad_idx    = (const int*)d_in[4];
    const float* Wq         = (const float*)d_in[5];
    const float* bq         = (const float*)d_in[6];
    const float* Wk         = (const float*)d_in[7];
    /* d_in[8] bk unused (cancels in softmax) */
    const float* Wv         = (const float*)d_in[9];
    const float* bv         = (const float*)d_in[10];
    const float* Wo         = (const float*)d_in[11];
    const float* bo         = (const float*)d_in[12];
    float* out = (float*)d_out;

    int B = out_size / 64;

    cudaFuncSetAttribute(mha_state_encoder_kernel,
                         cudaFuncAttributeMaxDynamicSharedMemorySize, SMEM_BYTES);
    mha_state_encoder_kernel<<<GRID, NT, SMEM_BYTES>>>(
        node_embed, start_idx, end_idx, pad_idx,
        Wq, bq, Wk, Wv, bv, Wo, bo, out, B);
}

// round 5
// speedup vs baseline: 1.2182x; 1.2182x over previous
#include <cuda_runtime.h>
#include <math.h>

// Round 4: R2 skeleton + (no sNT) + (P5 reads each node row once, 4 heads/thread)
// + f32x2 packed P3/P4 with batch-interleaved raw/q. No fused attention (reg spills).

#define NT 256
#define GRID 148

typedef unsigned long long ull;

#define OFF_WKT   0        // [128][65]
#define OFF_WV    8320     // [64][128]
#define OFF_WO    16512    // [128][64]
#define OFF_BQ    24704    // 128
#define OFF_BV    24832    // 128
#define OFF_BO    24960    // 64
#define OFF_N     25024    // [4][20][68] row-major padded (stride 68 floats)
#define OFF_RAW   30464    // [192][4] batch-interleaved
#define OFF_Q     31232    // [128][4] batch-interleaved (scale 0.25 folded in)
#define OFF_QK    31744    // [4][8][72]
#define OFF_SC    34048    // [4][8][24]
#define OFF_M     34816    // [4][8][72]
#define OFF_CTX   37120    // [4][128]
#define OFF_RED   37632    // 1024 floats scratch
#define OFF_V     38656    // [4][20]
#define OFF_MASK  38736    // [4][20]
#define SMEM_FLOATS 38816
#define SMEM_BYTES  (SMEM_FLOATS * 4)

__device__ __forceinline__ ull pk1(float a) {
    ull r; asm("mov.b64 %0, {%1,%1};" : "=l"(r) : "f"(a)); return r;
}
__device__ __forceinline__ void fma2(ull& d, ull a, ull b) {
    asm("fma.rn.f32x2 %0, %1, %2, %0;" : "+l"(d) : "l"(a), "l"(b));
}
__device__ __forceinline__ ull add2(ull a, ull b) {
    ull r; asm("add.rn.f32x2 %0, %1, %2;" : "=l"(r) : "l"(a), "l"(b)); return r;
}
__device__ __forceinline__ ull mul2(ull a, ull b) {
    ull r; asm("mul.rn.f32x2 %0, %1, %2;" : "=l"(r) : "l"(a), "l"(b)); return r;
}
__device__ __forceinline__ float2 upk(ull a) {
    float2 f; asm("mov.b64 {%0,%1}, %2;" : "=f"(f.x), "=f"(f.y) : "l"(a)); return f;
}

__global__ void __launch_bounds__(NT, 1)
mha_state_encoder_kernel(const float* __restrict__ node_embed,
                         const int*   __restrict__ start_idx,
                         const int*   __restrict__ end_idx,
                         const int*   __restrict__ pad_idx,
                         const float* __restrict__ Wq, const float* __restrict__ bq,
                         const float* __restrict__ Wk,
                         const float* __restrict__ Wv, const float* __restrict__ bv,
                         const float* __restrict__ Wo, const float* __restrict__ bo,
                         float* __restrict__ out, int B)
{
    extern __shared__ float sm[];
    float* sWKT = sm + OFF_WKT;
    float* sWV  = sm + OFF_WV;
    float* sWO  = sm + OFF_WO;
    float* sBQ  = sm + OFF_BQ;
    float* sBV  = sm + OFF_BV;
    float* sBO  = sm + OFF_BO;
    float* sN   = sm + OFF_N;
    float* sRAW = sm + OFF_RAW;
    float* sQ   = sm + OFF_Q;
    float* sQK  = sm + OFF_QK;
    float* sSC  = sm + OFF_SC;
    float* sM   = sm + OFF_M;
    float* sCTX = sm + OFF_CTX;
    float* sRED = sm + OFF_RED;
    float* sV   = sm + OFF_V;
    float* sMASK= sm + OFF_MASK;
    ull*   sRED2 = reinterpret_cast<ull*>(sRED);

    const int t = threadIdx.x;
    const int Q = B >> 2;

    for (int i = t; i < 8192; i += NT) {
        int d = i >> 7, c = i & 127;
        sWKT[c * 65 + d] = Wk[i];
    }
    for (int i = t; i < 2048; i += NT) {
        reinterpret_cast<float4*>(sWV)[i] = reinterpret_cast<const float4*>(Wv)[i];
        reinterpret_cast<float4*>(sWO)[i] = reinterpret_cast<const float4*>(Wo)[i];
    }
    if (t < 128) { sBQ[t] = bq[t]; sBV[t] = bv[t]; }
    if (t < 64)  sBO[t] = bo[t];

    const int c127 = t & 127;
    const int rh   = t >> 7;
    float wq[96];
    {
        const float* src = Wq + (size_t)(rh * 96) * 128 + c127;
        #pragma unroll
        for (int i = 0; i < 96; ++i) wq[i] = src[(size_t)i * 128];
    }

    const int gidx = t - 128;
    const int gnb  = (gidx >> 5) & 3;
    const int gwh  = (gidx >> 4) & 1;
    const int gdq  = gidx & 15;

    float4 pfN[5];
    float4 pfG = make_float4(0.f, 0.f, 0.f, 0.f);
    int    pfP = 0, gi_next = 0;

    int q0 = blockIdx.x;
    if (q0 < Q) {
        int b0 = q0 * 4;
        const float4* nsrc = reinterpret_cast<const float4*>(node_embed) + (size_t)b0 * 320;
        #pragma unroll
        for (int k = 0; k < 5; ++k) pfN[k] = nsrc[t + k * 256];
        if (t < 80) pfP = pad_idx[b0 * 20 + t];
        if (t >= 128) {
            int gi = gwh ? end_idx[b0 + gnb] : start_idx[b0 + gnb];
            pfG = *reinterpret_cast<const float4*>(node_embed + (size_t)gi * 64 + gdq * 4);
            int qn = q0 + GRID;
            if (qn < Q) gi_next = gwh ? end_idx[qn * 4 + gnb] : start_idx[qn * 4 + gnb];
        }
    }
    __syncthreads();

    for (int q = q0; q < Q; q += GRID) {
        const int b0 = q * 4;

        // ===== P1: commit prefetched data =====
        {
            float4* sN4 = reinterpret_cast<float4*>(sN);
            #pragma unroll
            for (int k = 0; k < 5; ++k) {
                int g   = t + k * 256;
                int nb  = g / 320;
                int rem = g - nb * 320;
                sN4[nb * 340 + (rem >> 4) * 17 + (rem & 15)] = pfN[k];
            }
            if (t < 80) sV[t] = (pfP >= 0) ? 1.0f : 0.0f;
            if (t >= 128) {
                int r0 = 64 + gwh * 64 + gdq * 4;
                sRAW[(r0 + 0) * 4 + gnb] = pfG.x;
                sRAW[(r0 + 1) * 4 + gnb] = pfG.y;
                sRAW[(r0 + 2) * 4 + gnb] = pfG.z;
                sRAW[(r0 + 3) * 4 + gnb] = pfG.w;
            }
        }
        {
            int qn = q + GRID;
            if (qn < Q) {
                int bn = qn * 4;
                const float4* nsrc = reinterpret_cast<const float4*>(node_embed) + (size_t)bn * 320;
                #pragma unroll
                for (int k = 0; k < 5; ++k) pfN[k] = nsrc[t + k * 256];
                if (t < 80) pfP = pad_idx[bn * 20 + t];
                if (t >= 128) {
                    pfG = *reinterpret_cast<const float4*>(node_embed + (size_t)gi_next * 64 + gdq * 4);
                    int qn2 = qn + GRID;
                    if (qn2 < Q) gi_next = gwh ? end_idx[qn2 * 4 + gnb] : start_idx[qn2 * 4 + gnb];
                }
            }
        }
        __syncthreads();

        // ===== P2: agg + mask =====
        if (t < 64) {
            int nb = t >> 4, dq = t & 15;
            const float4* col = reinterpret_cast<const float4*>(sN + nb * 1360) + dq;
            float ax = 0.f, ay = 0.f, az = 0.f, aw = 0.f;
            #pragma unroll
            for (int j = 0; j < 20; ++j) {
                float4 x = col[j * 17];
                ax += x.x; ay += x.y; az += x.z; aw += x.w;
            }
            int r0 = dq * 4;
            sRAW[(r0 + 0) * 4 + nb] = ax;
            sRAW[(r0 + 1) * 4 + nb] = ay;
            sRAW[(r0 + 2) * 4 + nb] = az;
            sRAW[(r0 + 3) * 4 + nb] = aw;
        } else if (t < 144) {
            int idx = t - 64, nb = idx / 20, j = idx - nb * 20;
            const float4* row = reinterpret_cast<const float4*>(sN + nb * 1360 + j * 68);
            float r0 = 0.f, r1 = 0.f;
            #pragma unroll
            for (int k = 0; k < 16; k += 2) {
                float4 a = row[k], b = row[k + 1];
                r0 += (a.x + a.y) + (a.z + a.w);
                r1 += (b.x + b.y) + (b.z + b.w);
            }
            sMASK[idx] = (sV[idx] == 0.f || (r0 + r1) == 0.f) ? 1.0f : 0.0f;
        }
        __syncthreads();

        // ===== P3: q = raw @ Wq (f32x2) =====
        {
            const ulonglong2* pR = reinterpret_cast<const ulonglong2*>(sRAW) + rh * 96;
            ull a01 = 0, a23 = 0;
            #pragma unroll
            for (int i = 0; i < 96; ++i) {
                ulonglong2 x = pR[i];
                ull wp = pk1(wq[i]);
                fma2(a01, wp, x.x);
                fma2(a23, wp, x.y);
            }
            sRED2[rh * 256 + c127 * 2 + 0] = a01;
            sRED2[rh * 256 + c127 * 2 + 1] = a23;
        }
        __syncthreads();
        {
            int c = t >> 1;
            ull v = add2(sRED2[t], sRED2[256 + t]);
            v = add2(v, pk1(sBQ[c]));
            v = mul2(v, pk1(0.25f));
            reinterpret_cast<ull*>(sQ)[t] = v;
        }
        __syncthreads();

        // ===== P4: qk (f32x2) =====
        #pragma unroll
        for (int p = 0; p < 2; ++p) {
            int u = t + p * 256;
            int h = u >> 6, d = u & 63;
            const float* wkb = sWKT + h * 16 * 65 + d;
            const ulonglong2* q2 = reinterpret_cast<const ulonglong2*>(sQ) + h * 16;
            ull a01 = 0, a23 = 0;
            #pragma unroll
            for (int i = 0; i < 16; ++i) {
                ull wp = pk1(wkb[i * 65]);
                ulonglong2 qv = q2[i];
                fma2(a01, wp, qv.x);
                fma2(a23, wp, qv.y);
            }
            float2 f01 = upk(a01), f23 = upk(a23);
            sQK[0 * 576 + h * 72 + d] = f01.x;
            sQK[1 * 576 + h * 72 + d] = f01.y;
            sQK[2 * 576 + h * 72 + d] = f23.x;
            sQK[3 * 576 + h * 72 + d] = f23.y;
        }
        __syncthreads();

        // ===== P5: scores, node row read once per thread, 4 heads =====
        if (t < 160) {
            int nb = t / 40;
            int r  = t - nb * 40;
            int j  = r >> 1;
            int hh = r & 1;
            const float4* n4  = reinterpret_cast<const float4*>(sN + nb * 1360 + j * 68);
            const float*  qkb = sQK + nb * 576 + (hh * 4) * 72;
            float s0 = 0.f, s1 = 0.f, s2 = 0.f, s3 = 0.f;
            #pragma unroll
            for (int k = 0; k < 16; ++k) {
                float4 x  = n4[k];
                float4 a0 = *reinterpret_cast<const float4*>(qkb + 0 * 72 + k * 4);
                float4 a1 = *reinterpret_cast<const float4*>(qkb + 1 * 72 + k * 4);
                float4 a2 = *reinterpret_cast<const float4*>(qkb + 2 * 72 + k * 4);
                float4 a3 = *reinterpret_cast<const float4*>(qkb + 3 * 72 + k * 4);
                s0 = fmaf(a0.x,x.x,s0); s0 = fmaf(a0.y,x.y,s0); s0 = fmaf(a0.z,x.z,s0); s0 = fmaf(a0.w,x.w,s0);
                s1 = fmaf(a1.x,x.x,s1); s1 = fmaf(a1.y,x.y,s1); s1 = fmaf(a1.z,x.z,s1); s1 = fmaf(a1.w,x.w,s1);
                s2 = fmaf(a2.x,x.x,s2); s2 = fmaf(a2.y,x.y,s2); s2 = fmaf(a2.z,x.z,s2); s2 = fmaf(a2.w,x.w,s2);
                s3 = fmaf(a3.x,x.x,s3); s3 = fmaf(a3.y,x.y,s3); s3 = fmaf(a3.z,x.z,s3); s3 = fmaf(a3.w,x.w,s3);
            }
            float msk = sMASK[nb * 20 + j] * (-1e9f);
            float* dst = sSC + nb * 192 + (hh * 4) * 24 + j;
            dst[0 * 24] = s0 + msk;
            dst[1 * 24] = s1 + msk;
            dst[2 * 24] = s2 + msk;
            dst[3 * 24] = s3 + msk;
        }
        __syncthreads();

        // ===== softmax per (nb, head) =====
        if (t < 32) {
            int nb = t >> 3, h = t & 7;
            float* row = sSC + nb * 192 + h * 24;
            const float* vd = sV + nb * 20;
            float mx = row[0];
            #pragma unroll
            for (int j = 1; j < 20; ++j) mx = fmaxf(mx, row[j]);
            float ssum = 0.f;
            #pragma unroll
            for (int j = 0; j < 20; ++j) {
                float e = __expf(row[j] - mx);
                row[j] = e;
                ssum += e;
            }
            float inv = __fdividef(1.f, ssum);
            #pragma unroll
            for (int j = 0; j < 20; ++j) row[j] = row[j] * inv * vd[j];
        }
        __syncthreads();

        // ===== P6: m[nb][h][d] = sum_j attn * n[j][d] =====
        {
            #pragma unroll
            for (int u = t; u < 512; u += NT) {
                int dq = u & 15, h = (u >> 4) & 7, nb = u >> 7;
                const float* arow = sSC + nb * 192 + h * 24;
                const float4* n4  = reinterpret_cast<const float4*>(sN + nb * 1360);
                float mx_ = 0.f, my_ = 0.f, mz_ = 0.f, mw_ = 0.f;
                #pragma unroll
                for (int jq = 0; jq < 5; ++jq) {
                    float4 a  = *reinterpret_cast<const float4*>(arow + jq * 4);
                    float4 b0 = n4[(jq*4+0)*17 + dq];
                    float4 b1 = n4[(jq*4+1)*17 + dq];
                    float4 b2 = n4[(jq*4+2)*17 + dq];
                    float4 b3 = n4[(jq*4+3)*17 + dq];
                    mx_ = fmaf(a.x,b0.x,mx_); my_ = fmaf(a.x,b0.y,my_); mz_ = fmaf(a.x,b0.z,mz_); mw_ = fmaf(a.x,b0.w,mw_);
                    mx_ = fmaf(a.y,b1.x,mx_); my_ = fmaf(a.y,b1.y,my_); mz_ = fmaf(a.y,b1.z,mz_); mw_ = fmaf(a.y,b1.w,mw_);
                    mx_ = fmaf(a.z,b2.x,mx_); my_ = fmaf(a.z,b2.y,my_); mz_ = fmaf(a.z,b2.z,mz_); mw_ = fmaf(a.z,b2.w,mw_);
                    mx_ = fmaf(a.w,b3.x,mx_); my_ = fmaf(a.w,b3.y,my_); mz_ = fmaf(a.w,b3.z,mz_); mw_ = fmaf(a.w,b3.w,mw_);
                }
                *reinterpret_cast<float4*>(sM + nb*576 + h*72 + dq*4) = make_float4(mx_, my_, mz_, mw_);
            }
        }
        __syncthreads();

        // ===== P7: ctx =====
        {
            int cc = t & 127, dh = t >> 7, d0 = dh * 32, h = cc >> 4;
            const float* wv = sWV + d0 * 128 + cc;
            float a0 = 0.f, a1 = 0.f, a2 = 0.f, a3 = 0.f;
            #pragma unroll
            for (int k = 0; k < 8; ++k) {
                float w0 = wv[(k*4+0)*128], w1 = wv[(k*4+1)*128];
                float w2 = wv[(k*4+2)*128], w3 = wv[(k*4+3)*128];
                float4 m0 = *reinterpret_cast<const float4*>(sM + 0*576 + h*72 + d0 + k*4);
                float4 m1 = *reinterpret_cast<const float4*>(sM + 1*576 + h*72 + d0 + k*4);
                float4 m2 = *reinterpret_cast<const float4*>(sM + 2*576 + h*72 + d0 + k*4);
                float4 m3 = *reinterpret_cast<const float4*>(sM + 3*576 + h*72 + d0 + k*4);
                a0 = fmaf(w0,m0.x,a0); a0 = fmaf(w1,m0.y,a0); a0 = fmaf(w2,m0.z,a0); a0 = fmaf(w3,m0.w,a0);
                a1 = fmaf(w0,m1.x,a1); a1 = fmaf(w1,m1.y,a1); a1 = fmaf(w2,m1.z,a1); a1 = fmaf(w3,m1.w,a1);
                a2 = fmaf(w0,m2.x,a2); a2 = fmaf(w1,m2.y,a2); a2 = fmaf(w2,m2.z,a2); a2 = fmaf(w3,m2.w,a2);
                a3 = fmaf(w0,m3.x,a3); a3 = fmaf(w1,m3.y,a3); a3 = fmaf(w2,m3.z,a3); a3 = fmaf(w3,m3.w,a3);
            }
            sRED[(dh*4 + 0) * 128 + cc] = a0;
            sRED[(dh*4 + 1) * 128 + cc] = a1;
            sRED[(dh*4 + 2) * 128 + cc] = a2;
            sRED[(dh*4 + 3) * 128 + cc] = a3;
        }
        __syncthreads();
        {
            #pragma unroll
            for (int e = t; e < 512; e += NT) {
                int nb = e >> 7, cc = e & 127;
                sCTX[nb * 128 + cc] = sRED[nb * 128 + cc] + sRED[(4 + nb) * 128 + cc] + sBV[cc];
            }
        }
        __syncthreads();

        // ===== P8: out =====
        {
            int o = t & 63, cg = t >> 6, c0 = cg * 32;
            const float* wo = sWO + c0 * 64 + o;
            float a0 = 0.f, a1 = 0.f, a2 = 0.f, a3 = 0.f;
            #pragma unroll
            for (int k = 0; k < 8; ++k) {
                float w0 = wo[(k*4+0)*64], w1 = wo[(k*4+1)*64];
                float w2 = wo[(k*4+2)*64], w3 = wo[(k*4+3)*64];
                float4 x0 = *reinterpret_cast<const float4*>(sCTX + 0*128 + c0 + k*4);
                float4 x1 = *reinterpret_cast<const float4*>(sCTX + 1*128 + c0 + k*4);
                float4 x2 = *reinterpret_cast<const float4*>(sCTX + 2*128 + c0 + k*4);
                float4 x3 = *reinterpret_cast<const float4*>(sCTX + 3*128 + c0 + k*4);
                a0 = fmaf(w0,x0.x,a0); a0 = fmaf(w1,x0.y,a0); a0 = fmaf(w2,x0.z,a0); a0 = fmaf(w3,x0.w,a0);
                a1 = fmaf(w0,x1.x,a1); a1 = fmaf(w1,x1.y,a1); a1 = fmaf(w2,x1.z,a1); a1 = fmaf(w3,x1.w,a1);
                a2 = fmaf(w0,x2.x,a2); a2 = fmaf(w1,x2.y,a2); a2 = fmaf(w2,x2.z,a2); a2 = fmaf(w3,x2.w,a2);
                a3 = fmaf(w0,x3.x,a3); a3 = fmaf(w1,x3.y,a3); a3 = fmaf(w2,x3.z,a3); a3 = fmaf(w3,x3.w,a3);
            }
            sRED[(cg*4 + 0) * 64 + o] = a0;
            sRED[(cg*4 + 1) * 64 + o] = a1;
            sRED[(cg*4 + 2) * 64 + o] = a2;
            sRED[(cg*4 + 3) * 64 + o] = a3;
        }
        __syncthreads();
        {
            int nb = t >> 6, o = t & 63;
            float s = ((sRED[(0*4+nb)*64+o] + sRED[(1*4+nb)*64+o]) +
                       (sRED[(2*4+nb)*64+o] + sRED[(3*4+nb)*64+o])) + sBO[o];
            out[(size_t)(b0 + nb) * 64 + o] = s;
        }
    }
}

extern "C" void kernel_launch(void* const* d_in, const int* in_sizes, int n_in,
                              void* d_out, int out_size)
{
    const float* node_embed = (const float*)d_in[0];
    const int*   start_idx  = (const int*)d_in[1];
    const int*   end_idx    = (const int*)d_in[2];
    /* d_in[3] seg_ids unused (structural) */
    const int*   pad_idx    = (const int*)d_in[4];
    const float* Wq         = (const float*)d_in[5];
    const float* bq         = (const float*)d_in[6];
    const float* Wk         = (const float*)d_in[7];
    /* d_in[8] bk unused (cancels in softmax) */
    const float* Wv         = (const float*)d_in[9];
    const float* bv         = (const float*)d_in[10];
    const float* Wo         = (const float*)d_in[11];
    const float* bo         = (const float*)d_in[12];
    float* out = (float*)d_out;

    int B = out_size / 64;

    cudaFuncSetAttribute(mha_state_encoder_kernel,
                         cudaFuncAttributeMaxDynamicSharedMemorySize, SMEM_BYTES);
    mha_state_encoder_kernel<<<GRID, NT, SMEM_BYTES>>>(
        node_embed, start_idx, end_idx, pad_idx,
        Wq, bq, Wk, Wv, bv, Wo, bo, out, B);
}

// round 6
// speedup vs baseline: 1.2514x; 1.0272x over previous
#include <cuda_runtime.h>
#include <math.h>

// Round 5: NB=8 batches/iter, NT=512 (16 warps, occ 25%), Wq split 4-way into
// registers (48/thread), f32x2 P3/P4, weights amortized over 8 batches.

#define NT 512
#define GRID 148

typedef unsigned long long ull;

#define OFF_WKT   0        // [128][65]  = 8320
#define OFF_WV    8320     // [64][128]  = 8192
#define OFF_WO    16512    // [128][64]  = 8192
#define OFF_BQ    24704    // 128
#define OFF_BV    24832    // 128
#define OFF_BO    24960    // 64
#define OFF_N     25024    // [8][20][68] = 10880
#define OFF_RAW   35904    // [192][8] batch-interleaved = 1536
#define OFF_Q     37440    // [128][8] batch-interleaved = 1024 (0.25 folded)
#define OFF_QK    38464    // [8][8][72] = 4608
#define OFF_SC    43072    // [8][8][28] = 1792 (stride 28: conflict-free softmax)
#define OFF_M     44864    // [8][8][72] = 4608
#define OFF_CTX   49472    // [8][128] = 1024
#define OFF_RED   50496    // 5120 floats scratch (P3 uses ull stride-5 layout)
#define OFF_V     55616    // [8][20] = 160
#define OFF_MASK  55776    // [8][20] = 160
#define SMEM_FLOATS 55936
#define SMEM_BYTES  (SMEM_FLOATS * 4)   // 223744 <= 227KB

__device__ __forceinline__ ull pk1(float a) {
    ull r; asm("mov.b64 %0, {%1,%1};" : "=l"(r) : "f"(a)); return r;
}
__device__ __forceinline__ void fma2(ull& d, ull a, ull b) {
    asm("fma.rn.f32x2 %0, %1, %2, %0;" : "+l"(d) : "l"(a), "l"(b));
}
__device__ __forceinline__ ull add2(ull a, ull b) {
    ull r; asm("add.rn.f32x2 %0, %1, %2;" : "=l"(r) : "l"(a), "l"(b)); return r;
}
__device__ __forceinline__ ull mul2(ull a, ull b) {
    ull r; asm("mul.rn.f32x2 %0, %1, %2;" : "=l"(r) : "l"(a), "l"(b)); return r;
}
__device__ __forceinline__ float2 upk(ull a) {
    float2 f; asm("mov.b64 {%0,%1}, %2;" : "=f"(f.x), "=f"(f.y) : "l"(a)); return f;
}

__global__ void __launch_bounds__(NT, 1)
mha_state_encoder_kernel(const float* __restrict__ node_embed,
                         const int*   __restrict__ start_idx,
                         const int*   __restrict__ end_idx,
                         const int*   __restrict__ pad_idx,
                         const float* __restrict__ Wq, const float* __restrict__ bq,
                         const float* __restrict__ Wk,
                         const float* __restrict__ Wv, const float* __restrict__ bv,
                         const float* __restrict__ Wo, const float* __restrict__ bo,
                         float* __restrict__ out, int B)
{
    extern __shared__ float sm[];
    float* sWKT = sm + OFF_WKT;
    float* sWV  = sm + OFF_WV;
    float* sWO  = sm + OFF_WO;
    float* sBQ  = sm + OFF_BQ;
    float* sBV  = sm + OFF_BV;
    float* sBO  = sm + OFF_BO;
    float* sN   = sm + OFF_N;
    float* sRAW = sm + OFF_RAW;
    float* sQ   = sm + OFF_Q;
    float* sQK  = sm + OFF_QK;
    float* sSC  = sm + OFF_SC;
    float* sM   = sm + OFF_M;
    float* sCTX = sm + OFF_CTX;
    float* sRED = sm + OFF_RED;
    float* sV   = sm + OFF_V;
    float* sMASK= sm + OFF_MASK;
    ull*   sRED2 = reinterpret_cast<ull*>(sRED);
    ull*   sQ2   = reinterpret_cast<ull*>(sQ);

    const int t = threadIdx.x;
    const int Q = B >> 3;                 // 8-batch groups

    // ---- stage weights ----
    for (int i = t; i < 8192; i += NT) {
        int d = i >> 7, c = i & 127;
        sWKT[c * 65 + d] = Wk[i];
    }
    for (int i = t; i < 2048; i += NT) {
        reinterpret_cast<float4*>(sWV)[i] = reinterpret_cast<const float4*>(Wv)[i];
        reinterpret_cast<float4*>(sWO)[i] = reinterpret_cast<const float4*>(Wo)[i];
    }
    if (t < 128) { sBQ[t] = bq[t]; sBV[t] = bv[t]; }
    if (t < 64)  sBO[t] = bo[t];

    // Wq register slice: column c127, rows rg*48..+47  (4-way row split)
    const int c127 = t & 127;
    const int rg   = t >> 7;              // 0..3
    float wq[48];
    {
        const float* src = Wq + (size_t)(rg * 48) * 128 + c127;
        #pragma unroll
        for (int i = 0; i < 48; ++i) wq[i] = src[(size_t)i * 128];
    }

    // gather thread geometry (t in [256,512)): gnb fastest (bank spread)
    const int gidx = t - 256;
    const int gnb  = gidx & 7;
    const int gwh  = (gidx >> 3) & 1;
    const int gdq  = gidx >> 4;           // 0..15

    // prefetch state
    float4 pfN[5];
    float4 pfG = make_float4(0.f, 0.f, 0.f, 0.f);
    int    pfP = 0, gi_next = 0;

    int q0 = blockIdx.x;
    if (q0 < Q) {
        int b0 = q0 * 8;
        const float4* nsrc = reinterpret_cast<const float4*>(node_embed) + (size_t)b0 * 320;
        #pragma unroll
        for (int k = 0; k < 5; ++k) pfN[k] = nsrc[t + k * 512];
        if (t < 160) pfP = pad_idx[b0 * 20 + t];
        if (t >= 256) {
            int gi = gwh ? end_idx[b0 + gnb] : start_idx[b0 + gnb];
            pfG = *reinterpret_cast<const float4*>(node_embed + (size_t)gi * 64 + gdq * 4);
            int qn = q0 + GRID;
            if (qn < Q) gi_next = gwh ? end_idx[qn * 8 + gnb] : start_idx[qn * 8 + gnb];
        }
    }
    __syncthreads();

    for (int q = q0; q < Q; q += GRID) {
        const int b0 = q * 8;

        // ===== P1: commit prefetched data =====
        {
            float4* sN4 = reinterpret_cast<float4*>(sN);
            #pragma unroll
            for (int k = 0; k < 5; ++k) {
                int g   = t + k * 512;
                int nb  = g / 320;
                int rem = g - nb * 320;
                sN4[nb * 340 + (rem >> 4) * 17 + (rem & 15)] = pfN[k];
            }
            if (t < 160) sV[t] = (pfP >= 0) ? 1.0f : 0.0f;
            if (t >= 256) {
                int r0 = 64 + gwh * 64 + gdq * 4;
                sRAW[(r0 + 0) * 8 + gnb] = pfG.x;
                sRAW[(r0 + 1) * 8 + gnb] = pfG.y;
                sRAW[(r0 + 2) * 8 + gnb] = pfG.z;
                sRAW[(r0 + 3) * 8 + gnb] = pfG.w;
            }
        }
        // issue next-group prefetch
        {
            int qn = q + GRID;
            if (qn < Q) {
                int bn = qn * 8;
                const float4* nsrc = reinterpret_cast<const float4*>(node_embed) + (size_t)bn * 320;
                #pragma unroll
                for (int k = 0; k < 5; ++k) pfN[k] = nsrc[t + k * 512];
                if (t < 160) pfP = pad_idx[bn * 20 + t];
                if (t >= 256) {
                    pfG = *reinterpret_cast<const float4*>(node_embed + (size_t)gi_next * 64 + gdq * 4);
                    int qn2 = qn + GRID;
                    if (qn2 < Q) gi_next = gwh ? end_idx[qn2 * 8 + gnb] : start_idx[qn2 * 8 + gnb];
                }
            }
        }
        __syncthreads();

        // ===== P2: agg (t<128) + mask (t in [128,288)) =====
        if (t < 128) {
            int nb = t >> 4, dq = t & 15;
            const float4* col = reinterpret_cast<const float4*>(sN + nb * 1360) + dq;
            float ax = 0.f, ay = 0.f, az = 0.f, aw = 0.f;
            #pragma unroll
            for (int j = 0; j < 20; ++j) {
                float4 x = col[j * 17];
                ax += x.x; ay += x.y; az += x.z; aw += x.w;
            }
            int r0 = dq * 4;
            sRAW[(r0 + 0) * 8 + nb] = ax;
            sRAW[(r0 + 1) * 8 + nb] = ay;
            sRAW[(r0 + 2) * 8 + nb] = az;
            sRAW[(r0 + 3) * 8 + nb] = aw;
        } else if (t < 288) {
            int idx = t - 128, nb = idx / 20, j = idx - nb * 20;
            const float4* row = reinterpret_cast<const float4*>(sN + nb * 1360 + j * 68);
            float r0 = 0.f, r1 = 0.f;
            #pragma unroll
            for (int k = 0; k < 16; k += 2) {
                float4 a = row[k], b = row[k + 1];
                r0 += (a.x + a.y) + (a.z + a.w);
                r1 += (b.x + b.y) + (b.z + b.w);
            }
            sMASK[idx] = (sV[idx] == 0.f || (r0 + r1) == 0.f) ? 1.0f : 0.0f;
        }
        __syncthreads();

        // ===== P3: q = raw @ Wq (f32x2, 48 rows/thread, 8 batches) =====
        {
            const ulonglong2* pR = reinterpret_cast<const ulonglong2*>(sRAW) + rg * 96;
            ull a01 = 0, a23 = 0, a45 = 0, a67 = 0;
            #pragma unroll
            for (int i = 0; i < 48; ++i) {
                ulonglong2 x = pR[2 * i];
                ulonglong2 y = pR[2 * i + 1];
                ull wp = pk1(wq[i]);
                fma2(a01, wp, x.x);
                fma2(a23, wp, x.y);
                fma2(a45, wp, y.x);
                fma2(a67, wp, y.y);
            }
            ull* dst = sRED2 + rg * 640 + c127 * 5;   // stride-5: bank-spread
            dst[0] = a01; dst[1] = a23; dst[2] = a45; dst[3] = a67;
        }
        __syncthreads();
        {   // combine + bias + fold 0.25 scale; sQ layout ull[c][4]
            int c = t >> 2, pp = t & 3;
            ull v = add2(add2(sRED2[c * 5 + pp], sRED2[640 + c * 5 + pp]),
                         add2(sRED2[1280 + c * 5 + pp], sRED2[1920 + c * 5 + pp]));
            v = add2(v, pk1(sBQ[c]));
            v = mul2(v, pk1(0.25f));
            sQ2[t] = v;
        }
        __syncthreads();

        // ===== P4: qk[nb][h][d] (f32x2) =====
        {
            int h = t >> 6, d = t & 63;
            const float* wkb = sWKT + h * 16 * 65 + d;
            const ulonglong2* q2 = reinterpret_cast<const ulonglong2*>(sQ) + h * 16 * 2;
            ull a01 = 0, a23 = 0, a45 = 0, a67 = 0;
            #pragma unroll
            for (int i = 0; i < 16; ++i) {
                ull wp = pk1(wkb[i * 65]);
                ulonglong2 x = q2[2 * i];
                ulonglong2 y = q2[2 * i + 1];
                fma2(a01, wp, x.x);
                fma2(a23, wp, x.y);
                fma2(a45, wp, y.x);
                fma2(a67, wp, y.y);
            }
            float2 f01 = upk(a01), f23 = upk(a23), f45 = upk(a45), f67 = upk(a67);
            float* dst = sQK + h * 72 + d;
            dst[0 * 576] = f01.x; dst[1 * 576] = f01.y;
            dst[2 * 576] = f23.x; dst[3 * 576] = f23.y;
            dst[4 * 576] = f45.x; dst[5 * 576] = f45.y;
            dst[6 * 576] = f67.x; dst[7 * 576] = f67.y;
        }
        __syncthreads();

        // ===== P5: scores — node row read once, 4 heads/thread =====
        if (t < 320) {
            int nb = t / 40;
            int r  = t - nb * 40;
            int j  = r >> 1;
            int hh = r & 1;
            const float4* n4  = reinterpret_cast<const float4*>(sN + nb * 1360 + j * 68);
            const float*  qkb = sQK + nb * 576 + (hh * 4) * 72;
            float s0 = 0.f, s1 = 0.f, s2 = 0.f, s3 = 0.f;
            #pragma unroll
            for (int k = 0; k < 16; ++k) {
                float4 x  = n4[k];
                float4 a0 = *reinterpret_cast<const float4*>(qkb + 0 * 72 + k * 4);
                float4 a1 = *reinterpret_cast<const float4*>(qkb + 1 * 72 + k * 4);
                float4 a2 = *reinterpret_cast<const float4*>(qkb + 2 * 72 + k * 4);
                float4 a3 = *reinterpret_cast<const float4*>(qkb + 3 * 72 + k * 4);
                s0 = fmaf(a0.x,x.x,s0); s0 = fmaf(a0.y,x.y,s0); s0 = fmaf(a0.z,x.z,s0); s0 = fmaf(a0.w,x.w,s0);
                s1 = fmaf(a1.x,x.x,s1); s1 = fmaf(a1.y,x.y,s1); s1 = fmaf(a1.z,x.z,s1); s1 = fmaf(a1.w,x.w,s1);
                s2 = fmaf(a2.x,x.x,s2); s2 = fmaf(a2.y,x.y,s2); s2 = fmaf(a2.z,x.z,s2); s2 = fmaf(a2.w,x.w,s2);
                s3 = fmaf(a3.x,x.x,s3); s3 = fmaf(a3.y,x.y,s3); s3 = fmaf(a3.z,x.z,s3); s3 = fmaf(a3.w,x.w,s3);
            }
            float msk = sMASK[nb * 20 + j] * (-1e9f);
            float* dst = sSC + nb * 224 + (hh * 4) * 28 + j;
            dst[0 * 28] = s0 + msk;
            dst[1 * 28] = s1 + msk;
            dst[2 * 28] = s2 + msk;
            dst[3 * 28] = s3 + msk;
        }
        __syncthreads();

        // ===== softmax per (nb, head) =====
        if (t < 64) {
            int nb = t >> 3, h = t & 7;
            float* row = sSC + nb * 224 + h * 28;
            const float* vd = sV + nb * 20;
            float mx = row[0];
            #pragma unroll
            for (int j = 1; j < 20; ++j) mx = fmaxf(mx, row[j]);
            float ssum = 0.f;
            #pragma unroll
            for (int j = 0; j < 20; ++j) {
                float e = __expf(row[j] - mx);
                row[j] = e;
                ssum += e;
            }
            float inv = __fdividef(1.f, ssum);
            #pragma unroll
            for (int j = 0; j < 20; ++j) row[j] = row[j] * inv * vd[j];
        }
        __syncthreads();

        // ===== P6: m[nb][h][d] = sum_j attn * n[j][d]  (1024 items / 512 thr) =====
        #pragma unroll
        for (int p = 0; p < 2; ++p) {
            int u  = t + p * 512;
            int dq = u & 15, h = (u >> 4) & 7, nb = u >> 7;
            const float* arow = sSC + nb * 224 + h * 28;
            const float4* n4  = reinterpret_cast<const float4*>(sN + nb * 1360);
            float mx_ = 0.f, my_ = 0.f, mz_ = 0.f, mw_ = 0.f;
            #pragma unroll
            for (int jq = 0; jq < 5; ++jq) {
                float4 a  = *reinterpret_cast<const float4*>(arow + jq * 4);
                float4 b0 = n4[(jq*4+0)*17 + dq];
                float4 b1 = n4[(jq*4+1)*17 + dq];
                float4 b2 = n4[(jq*4+2)*17 + dq];
                float4 b3 = n4[(jq*4+3)*17 + dq];
                mx_ = fmaf(a.x,b0.x,mx_); my_ = fmaf(a.x,b0.y,my_); mz_ = fmaf(a.x,b0.z,mz_); mw_ = fmaf(a.x,b0.w,mw_);
                mx_ = fmaf(a.y,b1.x,mx_); my_ = fmaf(a.y,b1.y,my_); mz_ = fmaf(a.y,b1.z,mz_); mw_ = fmaf(a.y,b1.w,mw_);
                mx_ = fmaf(a.z,b2.x,mx_); my_ = fmaf(a.z,b2.y,my_); mz_ = fmaf(a.z,b2.z,mz_); mw_ = fmaf(a.z,b2.w,mw_);
                mx_ = fmaf(a.w,b3.x,mx_); my_ = fmaf(a.w,b3.y,my_); mz_ = fmaf(a.w,b3.z,mz_); mw_ = fmaf(a.w,b3.w,mw_);
            }
            *reinterpret_cast<float4*>(sM + nb*576 + h*72 + dq*4) = make_float4(mx_, my_, mz_, mw_);
        }
        __syncthreads();

        // ===== P7: ctx partials — (cc, dh) over 16 d's, 8 batch accumulators =====
        {
            int cc = t & 127, dh = t >> 7, d0 = dh * 16, h = cc >> 4;
            float acc[8] = {0,0,0,0,0,0,0,0};
            #pragma unroll
            for (int kq = 0; kq < 4; ++kq) {
                int d = d0 + kq * 4;
                float w0 = sWV[(d+0)*128 + cc], w1 = sWV[(d+1)*128 + cc];
                float w2 = sWV[(d+2)*128 + cc], w3 = sWV[(d+3)*128 + cc];
                #pragma unroll
                for (int nb = 0; nb < 8; ++nb) {
                    float4 m = *reinterpret_cast<const float4*>(sM + nb*576 + h*72 + d);
                    acc[nb] = fmaf(w0, m.x, fmaf(w1, m.y, fmaf(w2, m.z, fmaf(w3, m.w, acc[nb]))));
                }
            }
            #pragma unroll
            for (int nb = 0; nb < 8; ++nb)
                sRED[dh * 1024 + nb * 128 + cc] = acc[nb];
        }
        __syncthreads();
        #pragma unroll
        for (int p = 0; p < 2; ++p) {   // combine ctx: 1024 items
            int e  = t + p * 512;
            int nb = e >> 7, cc = e & 127;
            sCTX[nb * 128 + cc] = ((sRED[nb*128+cc] + sRED[1024 + nb*128+cc]) +
                                   (sRED[2048 + nb*128+cc] + sRED[3072 + nb*128+cc])) + sBV[cc];
        }
        __syncthreads();

        // ===== P8: out partials — (o, cg) over 16 c's, 8 batch accumulators =====
        {
            int o = t & 63, cg = t >> 6, c0 = cg * 16;
            float acc[8] = {0,0,0,0,0,0,0,0};
            #pragma unroll
            for (int kq = 0; kq < 4; ++kq) {
                int c = c0 + kq * 4;
                float w0 = sWO[(c+0)*64 + o], w1 = sWO[(c+1)*64 + o];
                float w2 = sWO[(c+2)*64 + o], w3 = sWO[(c+3)*64 + o];
                #pragma unroll
                for (int nb = 0; nb < 8; ++nb) {
                    float4 x = *reinterpret_cast<const float4*>(sCTX + nb*128 + c);
                    acc[nb] = fmaf(w0, x.x, fmaf(w1, x.y, fmaf(w2, x.z, fmaf(w3, x.w, acc[nb]))));
                }
            }
            #pragma unroll
            for (int nb = 0; nb < 8; ++nb)
                sRED[cg * 512 + nb * 64 + o] = acc[nb];
        }
        __syncthreads();
        {   // final combine + store: 512 threads = (nb, o)
            int nb = t >> 6, o = t & 63;
            float s = 0.f;
            #pragma unroll
            for (int cg = 0; cg < 8; ++cg) s += sRED[cg * 512 + nb * 64 + o];
            out[(size_t)(b0 + nb) * 64 + o] = s + sBO[o];
        }
        // no trailing sync: next-iter P1 touches only sN/sV/sRAW, whose last
        // readers are >=2 barriers back; final store reads sRED/sBO only.
    }
}

extern "C" void kernel_launch(void* const* d_in, const int* in_sizes, int n_in,
                              void* d_out, int out_size)
{
    const float* node_embed = (const float*)d_in[0];
    const int*   start_idx  = (const int*)d_in[1];
    const int*   end_idx    = (const int*)d_in[2];
    /* d_in[3] seg_ids unused (structural) */
    const int*   pad_idx    = (const int*)d_in[4];
    const float* Wq         = (const float*)d_in[5];
    const float* bq         = (const float*)d_in[6];
    const float* Wk         = (const float*)d_in[7];
    /* d_in[8] bk unused (cancels in softmax) */
    const float* Wv         = (const float*)d_in[9];
    const float* bv         = (const float*)d_in[10];
    const float* Wo         = (const float*)d_in[11];
    const float* bo         = (const float*)d_in[12];
    float* out = (float*)d_out;

    int B = out_size / 64;

    cudaFuncSetAttribute(mha_state_encoder_kernel,
                         cudaFuncAttributeMaxDynamicSharedMemorySize, SMEM_BYTES);
    mha_state_encoder_kernel<<<GRID, NT, SMEM_BYTES>>>(
        node_embed, start_idx, end_idx, pad_idx,
        Wq, bq, Wk, Wv, bv, Wo, bo, out, B);
}

// round 7
// speedup vs baseline: 1.3531x; 1.0813x over previous
#include <cuda_runtime.h>
#include <math.h>

// Round 6: R5 skeleton + P6 4-heads/thread (node tile 8x -> 2x reads)
// + mask folded into P5 (P2 mask sub-phase removed).

#define NT 512
#define GRID 148

typedef unsigned long long ull;

#define OFF_WKT   0        // [128][65]  = 8320
#define OFF_WV    8320     // [64][128]  = 8192
#define OFF_WO    16512    // [128][64]  = 8192
#define OFF_BQ    24704    // 128
#define OFF_BV    24832    // 128
#define OFF_BO    24960    // 64
#define OFF_N     25024    // [8][20][68] = 10880
#define OFF_RAW   35904    // [192][8] batch-interleaved = 1536
#define OFF_Q     37440    // [128][8] batch-interleaved = 1024 (0.25 folded)
#define OFF_QK    38464    // [8][8][72] = 4608
#define OFF_SC    43072    // [8][8][28] = 1792
#define OFF_M     44864    // [8][8][72] = 4608
#define OFF_CTX   49472    // [8][128] = 1024
#define OFF_RED   50496    // 5120 floats scratch
#define OFF_V     55616    // [8][20] = 160
#define SMEM_FLOATS 55776
#define SMEM_BYTES  (SMEM_FLOATS * 4)

__device__ __forceinline__ ull pk1(float a) {
    ull r; asm("mov.b64 %0, {%1,%1};" : "=l"(r) : "f"(a)); return r;
}
__device__ __forceinline__ void fma2(ull& d, ull a, ull b) {
    asm("fma.rn.f32x2 %0, %1, %2, %0;" : "+l"(d) : "l"(a), "l"(b));
}
__device__ __forceinline__ ull add2(ull a, ull b) {
    ull r; asm("add.rn.f32x2 %0, %1, %2;" : "=l"(r) : "l"(a), "l"(b)); return r;
}
__device__ __forceinline__ ull mul2(ull a, ull b) {
    ull r; asm("mul.rn.f32x2 %0, %1, %2;" : "=l"(r) : "l"(a), "l"(b)); return r;
}
__device__ __forceinline__ float2 upk(ull a) {
    float2 f; asm("mov.b64 {%0,%1}, %2;" : "=f"(f.x), "=f"(f.y) : "l"(a)); return f;
}

__global__ void __launch_bounds__(NT, 1)
mha_state_encoder_kernel(const float* __restrict__ node_embed,
                         const int*   __restrict__ start_idx,
                         const int*   __restrict__ end_idx,
                         const int*   __restrict__ pad_idx,
                         const float* __restrict__ Wq, const float* __restrict__ bq,
                         const float* __restrict__ Wk,
                         const float* __restrict__ Wv, const float* __restrict__ bv,
                         const float* __restrict__ Wo, const float* __restrict__ bo,
                         float* __restrict__ out, int B)
{
    extern __shared__ float sm[];
    float* sWKT = sm + OFF_WKT;
    float* sWV  = sm + OFF_WV;
    float* sWO  = sm + OFF_WO;
    float* sBQ  = sm + OFF_BQ;
    float* sBV  = sm + OFF_BV;
    float* sBO  = sm + OFF_BO;
    float* sN   = sm + OFF_N;
    float* sRAW = sm + OFF_RAW;
    float* sQ   = sm + OFF_Q;
    float* sQK  = sm + OFF_QK;
    float* sSC  = sm + OFF_SC;
    float* sM   = sm + OFF_M;
    float* sCTX = sm + OFF_CTX;
    float* sRED = sm + OFF_RED;
    float* sV   = sm + OFF_V;
    ull*   sRED2 = reinterpret_cast<ull*>(sRED);
    ull*   sQ2   = reinterpret_cast<ull*>(sQ);

    const int t = threadIdx.x;
    const int Q = B >> 3;

    // ---- stage weights ----
    for (int i = t; i < 8192; i += NT) {
        int d = i >> 7, c = i & 127;
        sWKT[c * 65 + d] = Wk[i];
    }
    for (int i = t; i < 2048; i += NT) {
        reinterpret_cast<float4*>(sWV)[i] = reinterpret_cast<const float4*>(Wv)[i];
        reinterpret_cast<float4*>(sWO)[i] = reinterpret_cast<const float4*>(Wo)[i];
    }
    if (t < 128) { sBQ[t] = bq[t]; sBV[t] = bv[t]; }
    if (t < 64)  sBO[t] = bo[t];

    // Wq register slice
    const int c127 = t & 127;
    const int rg   = t >> 7;
    float wq[48];
    {
        const float* src = Wq + (size_t)(rg * 48) * 128 + c127;
        #pragma unroll
        for (int i = 0; i < 48; ++i) wq[i] = src[(size_t)i * 128];
    }

    // gather thread geometry (t in [256,512)), gnb fastest
    const int gidx = t - 256;
    const int gnb  = gidx & 7;
    const int gwh  = (gidx >> 3) & 1;
    const int gdq  = gidx >> 4;

    float4 pfN[5];
    float4 pfG = make_float4(0.f, 0.f, 0.f, 0.f);
    int    pfP = 0, gi_next = 0;

    int q0 = blockIdx.x;
    if (q0 < Q) {
        int b0 = q0 * 8;
        const float4* nsrc = reinterpret_cast<const float4*>(node_embed) + (size_t)b0 * 320;
        #pragma unroll
        for (int k = 0; k < 5; ++k) pfN[k] = nsrc[t + k * 512];
        if (t < 160) pfP = pad_idx[b0 * 20 + t];
        if (t >= 256) {
            int gi = gwh ? end_idx[b0 + gnb] : start_idx[b0 + gnb];
            pfG = *reinterpret_cast<const float4*>(node_embed + (size_t)gi * 64 + gdq * 4);
            int qn = q0 + GRID;
            if (qn < Q) gi_next = gwh ? end_idx[qn * 8 + gnb] : start_idx[qn * 8 + gnb];
        }
    }
    __syncthreads();

    for (int q = q0; q < Q; q += GRID) {
        const int b0 = q * 8;

        // ===== P1: commit prefetched data =====
        {
            float4* sN4 = reinterpret_cast<float4*>(sN);
            #pragma unroll
            for (int k = 0; k < 5; ++k) {
                int g   = t + k * 512;
                int nb  = g / 320;
                int rem = g - nb * 320;
                sN4[nb * 340 + (rem >> 4) * 17 + (rem & 15)] = pfN[k];
            }
            if (t < 160) sV[t] = (pfP >= 0) ? 1.0f : 0.0f;
            if (t >= 256) {
                int r0 = 64 + gwh * 64 + gdq * 4;
                sRAW[(r0 + 0) * 8 + gnb] = pfG.x;
                sRAW[(r0 + 1) * 8 + gnb] = pfG.y;
                sRAW[(r0 + 2) * 8 + gnb] = pfG.z;
                sRAW[(r0 + 3) * 8 + gnb] = pfG.w;
            }
        }
        // issue next-group prefetch
        {
            int qn = q + GRID;
            if (qn < Q) {
                int bn = qn * 8;
                const float4* nsrc = reinterpret_cast<const float4*>(node_embed) + (size_t)bn * 320;
                #pragma unroll
                for (int k = 0; k < 5; ++k) pfN[k] = nsrc[t + k * 512];
                if (t < 160) pfP = pad_idx[bn * 20 + t];
                if (t >= 256) {
                    pfG = *reinterpret_cast<const float4*>(node_embed + (size_t)gi_next * 64 + gdq * 4);
                    int qn2 = qn + GRID;
                    if (qn2 < Q) gi_next = gwh ? end_idx[qn2 * 8 + gnb] : start_idx[qn2 * 8 + gnb];
                }
            }
        }
        __syncthreads();

        // ===== P2: agg only (mask moved into P5) =====
        if (t < 128) {
            int nb = t >> 4, dq = t & 15;
            const float4* col = reinterpret_cast<const float4*>(sN + nb * 1360) + dq;
            float ax = 0.f, ay = 0.f, az = 0.f, aw = 0.f;
            #pragma unroll
            for (int j = 0; j < 20; ++j) {
                float4 x = col[j * 17];
                ax += x.x; ay += x.y; az += x.z; aw += x.w;
            }
            int r0 = dq * 4;
            sRAW[(r0 + 0) * 8 + nb] = ax;
            sRAW[(r0 + 1) * 8 + nb] = ay;
            sRAW[(r0 + 2) * 8 + nb] = az;
            sRAW[(r0 + 3) * 8 + nb] = aw;
        }
        __syncthreads();

        // ===== P3: q = raw @ Wq (f32x2) =====
        {
            const ulonglong2* pR = reinterpret_cast<const ulonglong2*>(sRAW) + rg * 96;
            ull a01 = 0, a23 = 0, a45 = 0, a67 = 0;
            #pragma unroll
            for (int i = 0; i < 48; ++i) {
                ulonglong2 x = pR[2 * i];
                ulonglong2 y = pR[2 * i + 1];
                ull wp = pk1(wq[i]);
                fma2(a01, wp, x.x);
                fma2(a23, wp, x.y);
                fma2(a45, wp, y.x);
                fma2(a67, wp, y.y);
            }
            ull* dst = sRED2 + rg * 640 + c127 * 5;
            dst[0] = a01; dst[1] = a23; dst[2] = a45; dst[3] = a67;
        }
        __syncthreads();
        {
            int c = t >> 2, pp = t & 3;
            ull v = add2(add2(sRED2[c * 5 + pp], sRED2[640 + c * 5 + pp]),
                         add2(sRED2[1280 + c * 5 + pp], sRED2[1920 + c * 5 + pp]));
            v = add2(v, pk1(sBQ[c]));
            v = mul2(v, pk1(0.25f));
            sQ2[t] = v;
        }
        __syncthreads();

        // ===== P4: qk[nb][h][d] (f32x2) =====
        {
            int h = t >> 6, d = t & 63;
            const float* wkb = sWKT + h * 16 * 65 + d;
            const ulonglong2* q2 = reinterpret_cast<const ulonglong2*>(sQ) + h * 16 * 2;
            ull a01 = 0, a23 = 0, a45 = 0, a67 = 0;
            #pragma unroll
            for (int i = 0; i < 16; ++i) {
                ull wp = pk1(wkb[i * 65]);
                ulonglong2 x = q2[2 * i];
                ulonglong2 y = q2[2 * i + 1];
                fma2(a01, wp, x.x);
                fma2(a23, wp, x.y);
                fma2(a45, wp, y.x);
                fma2(a67, wp, y.y);
            }
            float2 f01 = upk(a01), f23 = upk(a23), f45 = upk(a45), f67 = upk(a67);
            float* dst = sQK + h * 72 + d;
            dst[0 * 576] = f01.x; dst[1 * 576] = f01.y;
            dst[2 * 576] = f23.x; dst[3 * 576] = f23.y;
            dst[4 * 576] = f45.x; dst[5 * 576] = f45.y;
            dst[6 * 576] = f67.x; dst[7 * 576] = f67.y;
        }
        __syncthreads();

        // ===== P5: scores + inline mask (rowsum from already-loaded row) =====
        if (t < 320) {
            int nb = t / 40;
            int r  = t - nb * 40;
            int j  = r >> 1;
            int hh = r & 1;
            const float4* n4  = reinterpret_cast<const float4*>(sN + nb * 1360 + j * 68);
            const float*  qkb = sQK + nb * 576 + (hh * 4) * 72;
            float s0 = 0.f, s1 = 0.f, s2 = 0.f, s3 = 0.f, rsum = 0.f;
            #pragma unroll
            for (int k = 0; k < 16; ++k) {
                float4 x  = n4[k];
                rsum += (x.x + x.y) + (x.z + x.w);
                float4 a0 = *reinterpret_cast<const float4*>(qkb + 0 * 72 + k * 4);
                float4 a1 = *reinterpret_cast<const float4*>(qkb + 1 * 72 + k * 4);
                float4 a2 = *reinterpret_cast<const float4*>(qkb + 2 * 72 + k * 4);
                float4 a3 = *reinterpret_cast<const float4*>(qkb + 3 * 72 + k * 4);
                s0 = fmaf(a0.x,x.x,s0); s0 = fmaf(a0.y,x.y,s0); s0 = fmaf(a0.z,x.z,s0); s0 = fmaf(a0.w,x.w,s0);
                s1 = fmaf(a1.x,x.x,s1); s1 = fmaf(a1.y,x.y,s1); s1 = fmaf(a1.z,x.z,s1); s1 = fmaf(a1.w,x.w,s1);
                s2 = fmaf(a2.x,x.x,s2); s2 = fmaf(a2.y,x.y,s2); s2 = fmaf(a2.z,x.z,s2); s2 = fmaf(a2.w,x.w,s2);
                s3 = fmaf(a3.x,x.x,s3); s3 = fmaf(a3.y,x.y,s3); s3 = fmaf(a3.z,x.z,s3); s3 = fmaf(a3.w,x.w,s3);
            }
            float msk = (sV[nb * 20 + j] == 0.f || rsum == 0.f) ? -1e9f : 0.f;
            float* dst = sSC + nb * 224 + (hh * 4) * 28 + j;
            dst[0 * 28] = s0 + msk;
            dst[1 * 28] = s1 + msk;
            dst[2 * 28] = s2 + msk;
            dst[3 * 28] = s3 + msk;
        }
        __syncthreads();

        // ===== softmax per (nb, head) =====
        if (t < 64) {
            int nb = t >> 3, h = t & 7;
            float* row = sSC + nb * 224 + h * 28;
            const float* vd = sV + nb * 20;
            float mx = row[0];
            #pragma unroll
            for (int j = 1; j < 20; ++j) mx = fmaxf(mx, row[j]);
            float ssum = 0.f;
            #pragma unroll
            for (int j = 0; j < 20; ++j) {
                float e = __expf(row[j] - mx);
                row[j] = e;
                ssum += e;
            }
            float inv = __fdividef(1.f, ssum);
            #pragma unroll
            for (int j = 0; j < 20; ++j) row[j] = row[j] * inv * vd[j];
        }
        __syncthreads();

        // ===== P6: m — 4 heads/thread, warp = one batch (node tile read 2x) =====
        if (t < 256) {
            int nb = t >> 5, dq = (t >> 1) & 15, hg = t & 1;   // heads hg*4..+3
            const float4* n4 = reinterpret_cast<const float4*>(sN + nb * 1360) + dq;
            const float* a0 = sSC + nb * 224 + (hg * 4 + 0) * 28;
            const float* a1 = sSC + nb * 224 + (hg * 4 + 1) * 28;
            const float* a2 = sSC + nb * 224 + (hg * 4 + 2) * 28;
            const float* a3 = sSC + nb * 224 + (hg * 4 + 3) * 28;
            float4 m0 = make_float4(0,0,0,0), m1 = make_float4(0,0,0,0);
            float4 m2 = make_float4(0,0,0,0), m3 = make_float4(0,0,0,0);
            #pragma unroll
            for (int jq = 0; jq < 5; ++jq) {
                float4 w0 = *reinterpret_cast<const float4*>(a0 + jq * 4);
                float4 w1 = *reinterpret_cast<const float4*>(a1 + jq * 4);
                float4 w2 = *reinterpret_cast<const float4*>(a2 + jq * 4);
                float4 w3 = *reinterpret_cast<const float4*>(a3 + jq * 4);
                #pragma unroll
                for (int jj = 0; jj < 4; ++jj) {
                    float4 x = n4[(jq * 4 + jj) * 17];
                    float c0 = jj == 0 ? w0.x : jj == 1 ? w0.y : jj == 2 ? w0.z : w0.w;
                    float c1 = jj == 0 ? w1.x : jj == 1 ? w1.y : jj == 2 ? w1.z : w1.w;
                    float c2 = jj == 0 ? w2.x : jj == 1 ? w2.y : jj == 2 ? w2.z : w2.w;
                    float c3 = jj == 0 ? w3.x : jj == 1 ? w3.y : jj == 2 ? w3.z : w3.w;
                    m0.x = fmaf(c0,x.x,m0.x); m0.y = fmaf(c0,x.y,m0.y); m0.z = fmaf(c0,x.z,m0.z); m0.w = fmaf(c0,x.w,m0.w);
                    m1.x = fmaf(c1,x.x,m1.x); m1.y = fmaf(c1,x.y,m1.y); m1.z = fmaf(c1,x.z,m1.z); m1.w = fmaf(c1,x.w,m1.w);
                    m2.x = fmaf(c2,x.x,m2.x); m2.y = fmaf(c2,x.y,m2.y); m2.z = fmaf(c2,x.z,m2.z); m2.w = fmaf(c2,x.w,m2.w);
                    m3.x = fmaf(c3,x.x,m3.x); m3.y = fmaf(c3,x.y,m3.y); m3.z = fmaf(c3,x.z,m3.z); m3.w = fmaf(c3,x.w,m3.w);
                }
            }
            float* mb = sM + nb * 576 + (hg * 4) * 72 + dq * 4;
            *reinterpret_cast<float4*>(mb + 0 * 72) = m0;
            *reinterpret_cast<float4*>(mb + 1 * 72) = m1;
            *reinterpret_cast<float4*>(mb + 2 * 72) = m2;
            *reinterpret_cast<float4*>(mb + 3 * 72) = m3;
        }
        __syncthreads();

        // ===== P7: ctx partials =====
        {
            int cc = t & 127, dh = t >> 7, d0 = dh * 16, h = cc >> 4;
            float acc[8] = {0,0,0,0,0,0,0,0};
            #pragma unroll
            for (int kq = 0; kq < 4; ++kq) {
                int d = d0 + kq * 4;
                float w0 = sWV[(d+0)*128 + cc], w1 = sWV[(d+1)*128 + cc];
                float w2 = sWV[(d+2)*128 + cc], w3 = sWV[(d+3)*128 + cc];
                #pragma unroll
                for (int nb = 0; nb < 8; ++nb) {
                    float4 m = *reinterpret_cast<const float4*>(sM + nb*576 + h*72 + d);
                    acc[nb] = fmaf(w0, m.x, fmaf(w1, m.y, fmaf(w2, m.z, fmaf(w3, m.w, acc[nb]))));
                }
            }
            #pragma unroll
            for (int nb = 0; nb < 8; ++nb)
                sRED[dh * 1024 + nb * 128 + cc] = acc[nb];
        }
        __syncthreads();
        #pragma unroll
        for (int p = 0; p < 2; ++p) {
            int e  = t + p * 512;
            int nb = e >> 7, cc = e & 127;
            sCTX[nb * 128 + cc] = ((sRED[nb*128+cc] + sRED[1024 + nb*128+cc]) +
                                   (sRED[2048 + nb*128+cc] + sRED[3072 + nb*128+cc])) + sBV[cc];
        }
        __syncthreads();

        // ===== P8: out partials =====
        {
            int o = t & 63, cg = t >> 6, c0 = cg * 16;
            float acc[8] = {0,0,0,0,0,0,0,0};
            #pragma unroll
            for (int kq = 0; kq < 4; ++kq) {
                int c = c0 + kq * 4;
                float w0 = sWO[(c+0)*64 + o], w1 = sWO[(c+1)*64 + o];
                float w2 = sWO[(c+2)*64 + o], w3 = sWO[(c+3)*64 + o];
                #pragma unroll
                for (int nb = 0; nb < 8; ++nb) {
                    float4 x = *reinterpret_cast<const float4*>(sCTX + nb*128 + c);
                    acc[nb] = fmaf(w0, x.x, fmaf(w1, x.y, fmaf(w2, x.z, fmaf(w3, x.w, acc[nb]))));
                }
            }
            #pragma unroll
            for (int nb = 0; nb < 8; ++nb)
                sRED[cg * 512 + nb * 64 + o] = acc[nb];
        }
        __syncthreads();
        {
            int nb = t >> 6, o = t & 63;
            float s = 0.f;
            #pragma unroll
            for (int cg = 0; cg < 8; ++cg) s += sRED[cg * 512 + nb * 64 + o];
            out[(size_t)(b0 + nb) * 64 + o] = s + sBO[o];
        }
    }
}

extern "C" void kernel_launch(void* const* d_in, const int* in_sizes, int n_in,
                              void* d_out, int out_size)
{
    const float* node_embed = (const float*)d_in[0];
    const int*   start_idx  = (const int*)d_in[1];
    const int*   end_idx    = (const int*)d_in[2];
    /* d_in[3] seg_ids unused (structural) */
    const int*   pad_idx    = (const int*)d_in[4];
    const float* Wq         = (const float*)d_in[5];
    const float* bq         = (const float*)d_in[6];
    const float* Wk         = (const float*)d_in[7];
    /* d_in[8] bk unused (cancels in softmax) */
    const float* Wv         = (const float*)d_in[9];
    const float* bv         = (const float*)d_in[10];
    const float* Wo         = (const float*)d_in[11];
    const float* bo         = (const float*)d_in[12];
    float* out = (float*)d_out;

    int B = out_size / 64;

    cudaFuncSetAttribute(mha_state_encoder_kernel,
                         cudaFuncAttributeMaxDynamicSharedMemorySize, SMEM_BYTES);
    mha_state_encoder_kernel<<<GRID, NT, SMEM_BYTES>>>(
        node_embed, start_idx, end_idx, pad_idx,
        Wq, bq, Wk, Wv, bv, Wo, bo, out, B);
}